// round 9
// baseline (speedup 1.0000x reference)
#include <cuda_runtime.h>

// AtteMatchLay: multi-perspective cosine matching. N=8192 rows, D=768, P=20.
// out[n,p] = dot/(max(sqrt(n1),eps)*max(sqrt(n2),eps)), sums over d weighted by w[p,d]^2.
//
// Round-8: w2 table staged in SHARED MEMORY (eviction-proof, 29-cyc fixed LDS)
// instead of LDG (was falling to L2 @234cyc under streaming eviction).
// Block = 256 thr = 8 warps, all same P-group (pg = blockIdx.y); 30.75 KB smem w2
// filled once per block. Warp-tile = 2 rows (f32x2 row-packed) x 10 perspectives.
// 2-stage register prefetch on r/m streams; unroll-2; 128-reg cap -> 16 warps/SM.

#define PDIM  20
#define DDIM  768
#define PP    10
#define NITER (DDIM / 64)   // 12
#define EPS   1e-8f

typedef unsigned long long ull;

// ---- packed f32x2 helpers (only reachable via PTX) ----
__device__ __forceinline__ ull pack2(float x) {
    ull r; asm("mov.b64 %0, {%1, %1};" : "=l"(r) : "f"(x)); return r;
}
__device__ __forceinline__ ull packab(float a, float b) {
    ull r; asm("mov.b64 %0, {%1, %2};" : "=l"(r) : "f"(a), "f"(b)); return r;
}
__device__ __forceinline__ float2 u2f(ull v) {
    float2 f; asm("mov.b64 {%0, %1}, %2;" : "=f"(f.x), "=f"(f.y) : "l"(v)); return f;
}
__device__ __forceinline__ ull mul2(ull a, ull b) {
    ull r; asm("mul.rn.f32x2 %0, %1, %2;" : "=l"(r) : "l"(a), "l"(b)); return r;
}
__device__ __forceinline__ void fma2(ull& acc, ull a, ull b) {
    asm("fma.rn.f32x2 %0, %1, %2, %0;" : "+l"(acc) : "l"(a), "l"(b));
}
__device__ __forceinline__ ull add2(ull a, ull b) {
    ull r; asm("add.rn.f32x2 %0, %1, %2;" : "=l"(r) : "l"(a), "l"(b)); return r;
}

// Squared weights, [P][D] float layout (source for per-block smem staging).
__device__ float g_w2[PDIM * DDIM];

__global__ void prep_w2_kernel(const float* __restrict__ weight) {
    int t = blockIdx.x * blockDim.x + threadIdx.x;
    if (t < PDIM * DDIM) {
        float w = weight[t];
        g_w2[t] = w * w;
    }
}

__global__ void __launch_bounds__(256, 2)
cosmatch_kernel(const float* __restrict__ repres,
                const float* __restrict__ max_att,
                float* __restrict__ out,
                int N) {
    __shared__ float sw[PP * DDIM];   // 30.75 KB: this block's P-group w2

    const int tid  = threadIdx.x;
    const int warp = tid >> 5;
    const int lane = tid & 31;
    const int pg   = blockIdx.y;              // perspective group (0/1)
    const int rowbase = blockIdx.x * 16 + warp * 2;

    // ---- Stage w2 for this P-group into smem (1920 float4 copies) ----
    {
        const float4* src = (const float4*)(g_w2 + pg * PP * DDIM);
        float4* dst = (float4*)sw;
        for (int i = tid; i < PP * DDIM / 4; i += 256)
            dst[i] = src[i];
    }

    const float* rp = repres  + (size_t)rowbase * DDIM + lane * 2;
    const float* mp = max_att + (size_t)rowbase * DDIM + lane * 2;

    ull accd[PP], accr[PP], accm[PP];
#pragma unroll
    for (int p = 0; p < PP; p++) { accd[p] = 0ull; accr[p] = 0ull; accm[p] = 0ull; }

    // 2-stage data prefetch buffers (row0/row1 of r and m) — issued before sync
    float2 PR0[2], PR1[2], PM0[2], PM1[2];
#pragma unroll
    for (int s = 0; s < 2; s++) {
        PR0[s] = *(const float2*)(rp + s * 64);
        PR1[s] = *(const float2*)(rp + DDIM + s * 64);
        PM0[s] = *(const float2*)(mp + s * 64);
        PM1[s] = *(const float2*)(mp + DDIM + s * 64);
    }

    __syncthreads();   // w2 staged

    const float* ws = sw + lane * 2;

#pragma unroll 2
    for (int k = 0; k < NITER; k++) {
        const int buf = k & 1;

        const float2 R0 = PR0[buf], R1 = PR1[buf];
        const float2 M0 = PM0[buf], M1 = PM1[buf];

        // Branch-free deep prefetch for iteration k+2 (clamped; tail re-reads harmless)
        {
            int kp = k + 2; if (kp > NITER - 1) kp = NITER - 1;
            const int d = kp * 64;
            PR0[buf] = *(const float2*)(rp + d);
            PR1[buf] = *(const float2*)(rp + DDIM + d);
            PM0[buf] = *(const float2*)(mp + d);
            PM1[buf] = *(const float2*)(mp + DDIM + d);
        }

        const ull ra0 = packab(R0.x, R1.x), ra1 = packab(R0.y, R1.y);
        const ull ma0 = packab(M0.x, M1.x), ma1 = packab(M0.y, M1.y);
        const ull rm0 = mul2(ra0, ma0), rm1 = mul2(ra1, ma1);
        const ull rr0 = mul2(ra0, ra0), rr1 = mul2(ra1, ra1);
        const ull mm0 = mul2(ma0, ma0), mm1 = mul2(ma1, ma1);

        const float* wk = ws + k * 64;
#pragma unroll
        for (int p = 0; p < PP; p++) {
            const float2 w = *(const float2*)(wk + p * DDIM);   // LDS.64, conflict-free
            const ull wx = pack2(w.x);
            const ull wy = pack2(w.y);
            fma2(accd[p], rm0, wx);
            fma2(accd[p], rm1, wy);
            fma2(accr[p], rr0, wx);
            fma2(accr[p], rr1, wy);
            fma2(accm[p], mm0, wx);
            fma2(accm[p], mm1, wy);
        }
    }

    // Butterfly reduction across lanes (accumulators stay row-packed)
#pragma unroll
    for (int mask = 16; mask > 0; mask >>= 1) {
#pragma unroll
        for (int p = 0; p < PP; p++) {
            accd[p] = add2(accd[p], (ull)__shfl_xor_sync(0xFFFFFFFFu, accd[p], mask));
            accr[p] = add2(accr[p], (ull)__shfl_xor_sync(0xFFFFFFFFu, accr[p], mask));
            accm[p] = add2(accm[p], (ull)__shfl_xor_sync(0xFFFFFFFFu, accm[p], mask));
        }
    }

    // Epilogue: lane 0 writes 2 rows x 10 perspectives
    if (lane == 0 && rowbase < N) {
        float* o0 = out + (size_t)(rowbase + 0) * PDIM + pg * PP;
        float* o1 = out + (size_t)(rowbase + 1) * PDIM + pg * PP;
#pragma unroll
        for (int p = 0; p < PP; p++) {
            const float2 dd = u2f(accd[p]);
            const float2 n1 = u2f(accr[p]);
            const float2 n2 = u2f(accm[p]);
            o0[p] = dd.x / (fmaxf(sqrtf(n1.x), EPS) * fmaxf(sqrtf(n2.x), EPS));
            o1[p] = dd.y / (fmaxf(sqrtf(n1.y), EPS) * fmaxf(sqrtf(n2.y), EPS));
        }
    }
}

extern "C" void kernel_launch(void* const* d_in, const int* in_sizes, int n_in,
                              void* d_out, int out_size) {
    const float* repres  = (const float*)d_in[0];
    const float* max_att = (const float*)d_in[1];
    const float* weight  = (const float*)d_in[2];
    float* out = (float*)d_out;

    const int N = in_sizes[0] / DDIM;   // 8192 rows for the given shapes

    {
        const int total = PDIM * DDIM;
        prep_w2_kernel<<<(total + 255) / 256, 256>>>(weight);
    }
    {
        // 16 rows per block (8 warps x 2 rows), 2 P-group blocks per row-tile
        dim3 grid((N + 15) / 16, 2);
        cosmatch_kernel<<<grid, 256>>>(repres, max_att, out, N);
    }
}

// round 10
// speedup vs baseline: 1.6266x; 1.6266x over previous
#include <cuda_runtime.h>

// AtteMatchLay: multi-perspective cosine matching. N=8192 rows, D=768, P=20.
// out[n,p] = dot/(max(sqrt(n1),eps)*max(sqrt(n2),eps)), sums over d weighted by w[p,d]^2.
//
// Round-10: R7 structure (best: LDG w2 from L1, 2-stage reg prefetch, unroll-2) but
// warp-tile shrunk to 2 rows x 5 perspectives (4 P-groups) -> 15 ull accumulators
// = 30 regs -> target ~80 regs total -> 24 warps/SM (was 14 at 128 regs).
// Trades +14% instructions / +29% L1 wavefronts for +70% latency-hiding warps.

#define PDIM  20
#define DDIM  768
#define PP    5             // perspectives per warp (P-group size)
#define NPG   4             // number of P-groups
#define NITER (DDIM / 64)   // 12
#define EPS   1e-8f

typedef unsigned long long ull;

// ---- packed f32x2 helpers (only reachable via PTX) ----
__device__ __forceinline__ ull pack2(float x) {
    ull r; asm("mov.b64 %0, {%1, %1};" : "=l"(r) : "f"(x)); return r;
}
__device__ __forceinline__ ull packab(float a, float b) {
    ull r; asm("mov.b64 %0, {%1, %2};" : "=l"(r) : "f"(a), "f"(b)); return r;
}
__device__ __forceinline__ float2 u2f(ull v) {
    float2 f; asm("mov.b64 {%0, %1}, %2;" : "=f"(f.x), "=f"(f.y) : "l"(v)); return f;
}
__device__ __forceinline__ ull mul2(ull a, ull b) {
    ull r; asm("mul.rn.f32x2 %0, %1, %2;" : "=l"(r) : "l"(a), "l"(b)); return r;
}
__device__ __forceinline__ void fma2(ull& acc, ull a, ull b) {
    asm("fma.rn.f32x2 %0, %1, %2, %0;" : "+l"(acc) : "l"(a), "l"(b));
}
__device__ __forceinline__ ull add2(ull a, ull b) {
    ull r; asm("add.rn.f32x2 %0, %1, %2;" : "=l"(r) : "l"(a), "l"(b)); return r;
}

// Squared weights, [P][D] float layout (61.5 KB, L1/L2-resident).
__device__ float g_w2[PDIM * DDIM];

__global__ void prep_w2_kernel(const float* __restrict__ weight) {
    int t = blockIdx.x * blockDim.x + threadIdx.x;
    if (t < PDIM * DDIM) {
        float w = weight[t];
        g_w2[t] = w * w;
    }
}

__global__ void __launch_bounds__(128, 6)
cosmatch_kernel(const float* __restrict__ repres,
                const float* __restrict__ max_att,
                float* __restrict__ out,
                int N) {
    const int tid  = threadIdx.x;
    const int warp = tid >> 5;
    const int lane = tid & 31;
    const int pg   = blockIdx.y;              // perspective group (0..3)
    const int rowbase = blockIdx.x * 8 + warp * 2;

    const float* rp = repres  + (size_t)rowbase * DDIM + lane * 2;
    const float* mp = max_att + (size_t)rowbase * DDIM + lane * 2;
    const float* wg = g_w2 + pg * PP * DDIM + lane * 2;

    ull accd[PP], accr[PP], accm[PP];
#pragma unroll
    for (int p = 0; p < PP; p++) { accd[p] = 0ull; accr[p] = 0ull; accm[p] = 0ull; }

    // 2-stage data prefetch buffers (row0/row1 of r and m)
    float2 PR0[2], PR1[2], PM0[2], PM1[2];
#pragma unroll
    for (int s = 0; s < 2; s++) {
        PR0[s] = *(const float2*)(rp + s * 64);
        PR1[s] = *(const float2*)(rp + DDIM + s * 64);
        PM0[s] = *(const float2*)(mp + s * 64);
        PM1[s] = *(const float2*)(mp + DDIM + s * 64);
    }

#pragma unroll 2
    for (int k = 0; k < NITER; k++) {
        const int buf = k & 1;

        // Consume current stage
        const float2 R0 = PR0[buf], R1 = PR1[buf];
        const float2 M0 = PM0[buf], M1 = PM1[buf];

        // Branch-free deep prefetch for iteration k+2 (clamped; tail re-reads harmless)
        {
            int kp = k + 2; if (kp > NITER - 1) kp = NITER - 1;
            const int d = kp * 64;
            PR0[buf] = *(const float2*)(rp + d);
            PR1[buf] = *(const float2*)(rp + DDIM + d);
            PM0[buf] = *(const float2*)(mp + d);
            PM1[buf] = *(const float2*)(mp + DDIM + d);
        }

        const ull ra0 = packab(R0.x, R1.x), ra1 = packab(R0.y, R1.y);
        const ull ma0 = packab(M0.x, M1.x), ma1 = packab(M0.y, M1.y);
        const ull rm0 = mul2(ra0, ma0), rm1 = mul2(ra1, ma1);
        const ull rr0 = mul2(ra0, ra0), rr1 = mul2(ra1, ra1);
        const ull mm0 = mul2(ma0, ma0), mm1 = mul2(ma1, ma1);

        const float* wk = wg + k * 64;
#pragma unroll
        for (int p = 0; p < PP; p++) {
            const float2 w = *(const float2*)(wk + p * DDIM);   // L1-resident LDG.64
            const ull wx = pack2(w.x);
            const ull wy = pack2(w.y);
            fma2(accd[p], rm0, wx);
            fma2(accd[p], rm1, wy);
            fma2(accr[p], rr0, wx);
            fma2(accr[p], rr1, wy);
            fma2(accm[p], mm0, wx);
            fma2(accm[p], mm1, wy);
        }
    }

    // Butterfly reduction across lanes (accumulators stay row-packed)
#pragma unroll
    for (int mask = 16; mask > 0; mask >>= 1) {
#pragma unroll
        for (int p = 0; p < PP; p++) {
            accd[p] = add2(accd[p], (ull)__shfl_xor_sync(0xFFFFFFFFu, accd[p], mask));
            accr[p] = add2(accr[p], (ull)__shfl_xor_sync(0xFFFFFFFFu, accr[p], mask));
            accm[p] = add2(accm[p], (ull)__shfl_xor_sync(0xFFFFFFFFu, accm[p], mask));
        }
    }

    // Epilogue: lane 0 writes 2 rows x 5 perspectives
    if (lane == 0 && rowbase < N) {
        float* o0 = out + (size_t)(rowbase + 0) * PDIM + pg * PP;
        float* o1 = out + (size_t)(rowbase + 1) * PDIM + pg * PP;
#pragma unroll
        for (int p = 0; p < PP; p++) {
            const float2 dd = u2f(accd[p]);
            const float2 n1 = u2f(accr[p]);
            const float2 n2 = u2f(accm[p]);
            o0[p] = dd.x / (fmaxf(sqrtf(n1.x), EPS) * fmaxf(sqrtf(n2.x), EPS));
            o1[p] = dd.y / (fmaxf(sqrtf(n1.y), EPS) * fmaxf(sqrtf(n2.y), EPS));
        }
    }
}

extern "C" void kernel_launch(void* const* d_in, const int* in_sizes, int n_in,
                              void* d_out, int out_size) {
    const float* repres  = (const float*)d_in[0];
    const float* max_att = (const float*)d_in[1];
    const float* weight  = (const float*)d_in[2];
    float* out = (float*)d_out;

    const int N = in_sizes[0] / DDIM;   // 8192 rows for the given shapes

    {
        const int total = PDIM * DDIM;
        prep_w2_kernel<<<(total + 255) / 256, 256>>>(weight);
    }
    {
        // 8 rows per block (4 warps x 2 rows), 4 P-group blocks cover P=20
        dim3 grid((N + 7) / 8, NPG);
        cosmatch_kernel<<<grid, 128>>>(repres, max_att, out, N);
    }
}

// round 12
// speedup vs baseline: 1.6808x; 1.0333x over previous
#include <cuda_runtime.h>

// AtteMatchLay: multi-perspective cosine matching. N=8192 rows, D=768, P=20.
// out[n,p] = dot/(max(sqrt(n1),eps)*max(sqrt(n2),eps)), sums over d weighted by w[p,d]^2.
//
// Round-11: R10 (2 rows x 5 persp, 4 P-groups) + DOUBLE-BUFFERED w2 PREFETCH.
// Every load (data: 2 iters ahead; w2: 1 iter ahead) is issued before the fma
// block, which now runs entirely on resident registers -> L1tex queue latency
// is overlapped, not exposed. ~95 regs, launch_bounds(128,5) -> ~20 warps/SM.

#define PDIM  20
#define DDIM  768
#define PP    5             // perspectives per warp (P-group size)
#define NPG   4             // number of P-groups
#define NITER (DDIM / 64)   // 12
#define EPS   1e-8f

typedef unsigned long long ull;

// ---- packed f32x2 helpers (only reachable via PTX) ----
__device__ __forceinline__ ull pack2(float x) {
    ull r; asm("mov.b64 %0, {%1, %1};" : "=l"(r) : "f"(x)); return r;
}
__device__ __forceinline__ ull packab(float a, float b) {
    ull r; asm("mov.b64 %0, {%1, %2};" : "=l"(r) : "f"(a), "f"(b)); return r;
}
__device__ __forceinline__ float2 u2f(ull v) {
    float2 f; asm("mov.b64 {%0, %1}, %2;" : "=f"(f.x), "=f"(f.y) : "l"(v)); return f;
}
__device__ __forceinline__ ull mul2(ull a, ull b) {
    ull r; asm("mul.rn.f32x2 %0, %1, %2;" : "=l"(r) : "l"(a), "l"(b)); return r;
}
__device__ __forceinline__ void fma2(ull& acc, ull a, ull b) {
    asm("fma.rn.f32x2 %0, %1, %2, %0;" : "+l"(acc) : "l"(a), "l"(b));
}
__device__ __forceinline__ ull add2(ull a, ull b) {
    ull r; asm("add.rn.f32x2 %0, %1, %2;" : "=l"(r) : "l"(a), "l"(b)); return r;
}

// Squared weights, [P][D] float layout (61.5 KB, L1/L2-resident).
__device__ float g_w2[PDIM * DDIM];

__global__ void prep_w2_kernel(const float* __restrict__ weight) {
    int t = blockIdx.x * blockDim.x + threadIdx.x;
    if (t < PDIM * DDIM) {
        float w = weight[t];
        g_w2[t] = w * w;
    }
}

__global__ void __launch_bounds__(128, 5)
cosmatch_kernel(const float* __restrict__ repres,
                const float* __restrict__ max_att,
                float* __restrict__ out,
                int N) {
    const int tid  = threadIdx.x;
    const int warp = tid >> 5;
    const int lane = tid & 31;
    const int pg   = blockIdx.y;              // perspective group (0..3)
    const int rowbase = blockIdx.x * 8 + warp * 2;

    const float* rp = repres  + (size_t)rowbase * DDIM + lane * 2;
    const float* mp = max_att + (size_t)rowbase * DDIM + lane * 2;
    const float* wg = g_w2 + pg * PP * DDIM + lane * 2;

    ull accd[PP], accr[PP], accm[PP];
#pragma unroll
    for (int p = 0; p < PP; p++) { accd[p] = 0ull; accr[p] = 0ull; accm[p] = 0ull; }

    // 2-stage data prefetch buffers (row0/row1 of r and m)
    float2 PR0[2], PR1[2], PM0[2], PM1[2];
#pragma unroll
    for (int s = 0; s < 2; s++) {
        PR0[s] = *(const float2*)(rp + s * 64);
        PR1[s] = *(const float2*)(rp + DDIM + s * 64);
        PM0[s] = *(const float2*)(mp + s * 64);
        PM1[s] = *(const float2*)(mp + DDIM + s * 64);
    }

    // 1-stage (double-buffered) w2 prefetch
    float2 WB[2][PP];
#pragma unroll
    for (int p = 0; p < PP; p++)
        WB[0][p] = *(const float2*)(wg + p * DDIM);

#pragma unroll 2
    for (int k = 0; k < NITER; k++) {
        const int buf = k & 1;

        // Consume current stages (all resident in registers)
        const float2 R0 = PR0[buf], R1 = PR1[buf];
        const float2 M0 = PM0[buf], M1 = PM1[buf];
        float2 Wc[PP];
#pragma unroll
        for (int p = 0; p < PP; p++) Wc[p] = WB[buf][p];

        // Prefetch data for iteration k+2 (clamped; tail re-reads harmless)
        {
            int kp = k + 2; if (kp > NITER - 1) kp = NITER - 1;
            const int d = kp * 64;
            PR0[buf] = *(const float2*)(rp + d);
            PR1[buf] = *(const float2*)(rp + DDIM + d);
            PM0[buf] = *(const float2*)(mp + d);
            PM1[buf] = *(const float2*)(mp + DDIM + d);
        }
        // Prefetch w2 for iteration k+1 into the other buffer
        {
            int kp = k + 1; if (kp > NITER - 1) kp = NITER - 1;
            const float* wk = wg + kp * 64;
#pragma unroll
            for (int p = 0; p < PP; p++)
                WB[buf ^ 1][p] = *(const float2*)(wk + p * DDIM);
        }

        const ull ra0 = packab(R0.x, R1.x), ra1 = packab(R0.y, R1.y);
        const ull ma0 = packab(M0.x, M1.x), ma1 = packab(M0.y, M1.y);
        const ull rm0 = mul2(ra0, ma0), rm1 = mul2(ra1, ma1);
        const ull rr0 = mul2(ra0, ra0), rr1 = mul2(ra1, ra1);
        const ull mm0 = mul2(ma0, ma0), mm1 = mul2(ma1, ma1);

#pragma unroll
        for (int p = 0; p < PP; p++) {
            const ull wx = pack2(Wc[p].x);
            const ull wy = pack2(Wc[p].y);
            fma2(accd[p], rm0, wx);
            fma2(accd[p], rm1, wy);
            fma2(accr[p], rr0, wx);
            fma2(accr[p], rr1, wy);
            fma2(accm[p], mm0, wx);
            fma2(accm[p], mm1, wy);
        }
    }

    // Butterfly reduction across lanes (accumulators stay row-packed)
#pragma unroll
    for (int mask = 16; mask > 0; mask >>= 1) {
#pragma unroll
        for (int p = 0; p < PP; p++) {
            accd[p] = add2(accd[p], (ull)__shfl_xor_sync(0xFFFFFFFFu, accd[p], mask));
            accr[p] = add2(accr[p], (ull)__shfl_xor_sync(0xFFFFFFFFu, accr[p], mask));
            accm[p] = add2(accm[p], (ull)__shfl_xor_sync(0xFFFFFFFFu, accm[p], mask));
        }
    }

    // Epilogue: lane 0 writes 2 rows x 5 perspectives
    if (lane == 0 && rowbase < N) {
        float* o0 = out + (size_t)(rowbase + 0) * PDIM + pg * PP;
        float* o1 = out + (size_t)(rowbase + 1) * PDIM + pg * PP;
#pragma unroll
        for (int p = 0; p < PP; p++) {
            const float2 dd = u2f(accd[p]);
            const float2 n1 = u2f(accr[p]);
            const float2 n2 = u2f(accm[p]);
            o0[p] = dd.x / (fmaxf(sqrtf(n1.x), EPS) * fmaxf(sqrtf(n2.x), EPS));
            o1[p] = dd.y / (fmaxf(sqrtf(n1.y), EPS) * fmaxf(sqrtf(n2.y), EPS));
        }
    }
}

extern "C" void kernel_launch(void* const* d_in, const int* in_sizes, int n_in,
                              void* d_out, int out_size) {
    const float* repres  = (const float*)d_in[0];
    const float* max_att = (const float*)d_in[1];
    const float* weight  = (const float*)d_in[2];
    float* out = (float*)d_out;

    const int N = in_sizes[0] / DDIM;   // 8192 rows for the given shapes

    {
        const int total = PDIM * DDIM;
        prep_w2_kernel<<<(total + 255) / 256, 256>>>(weight);
    }
    {
        // 8 rows per block (4 warps x 2 rows), 4 P-group blocks cover P=20
        dim3 grid((N + 7) / 8, NPG);
        cosmatch_kernel<<<grid, 128>>>(repres, max_att, out, N);
    }
}